// round 1
// baseline (speedup 1.0000x reference)
#include <cuda_runtime.h>
#include <math.h>

#define BATCH 2
#define NNODE 50000
#define DIN 128
#define DOUT 64
#define NEDGE 800000
#define NEG_SLOPE 0.2f

// Scratch: h[which][b][node][d], which: 0 = key, 1 = value. 51.2 MB total.
__device__ float g_h[2ull * BATCH * NNODE * DOUT];
__device__ int g_row_ptr[NNODE + 1];

// ---------------------------------------------------------------------------
// GEMM: H = X @ W + b   for both (Xk,Wk,bk) and (Xv,Wv,bv), selected by blockIdx.y
// One thread computes one full output row (64 fp32 accumulators), W staged in smem.
// ---------------------------------------------------------------------------
__global__ void gemm_kernel(const float* __restrict__ Xk, const float* __restrict__ Xv,
                            const float* __restrict__ Wk, const float* __restrict__ bk,
                            const float* __restrict__ Wv, const float* __restrict__ bv)
{
    const int which = blockIdx.y;
    const float* __restrict__ X    = which ? Xv : Xk;
    const float* __restrict__ W    = which ? Wv : Wk;
    const float* __restrict__ bias = which ? bv : bk;
    float* __restrict__ H = g_h + (size_t)which * BATCH * NNODE * DOUT;

    __shared__ float Ws[DIN * DOUT];   // 32 KB
    __shared__ float bs[DOUT];
    for (int i = threadIdx.x; i < DIN * DOUT; i += blockDim.x) Ws[i] = W[i];
    if (threadIdx.x < DOUT) bs[threadIdx.x] = bias[threadIdx.x];
    __syncthreads();

    const int row = blockIdx.x * blockDim.x + threadIdx.x;
    if (row >= BATCH * NNODE) return;

    float acc[DOUT];
    #pragma unroll
    for (int j = 0; j < DOUT; j++) acc[j] = bs[j];

    const float4* __restrict__ Xrow = (const float4*)(X + (size_t)row * DIN);
    #pragma unroll 1
    for (int k4 = 0; k4 < DIN / 4; k4++) {
        float4 x = Xrow[k4];
        #pragma unroll
        for (int kk = 0; kk < 4; kk++) {
            float xv = (kk == 0) ? x.x : (kk == 1) ? x.y : (kk == 2) ? x.z : x.w;
            const float4* wrow = (const float4*)(Ws + (k4 * 4 + kk) * DOUT);
            #pragma unroll
            for (int j4 = 0; j4 < DOUT / 4; j4++) {
                float4 w = wrow[j4];
                acc[4*j4+0] = fmaf(xv, w.x, acc[4*j4+0]);
                acc[4*j4+1] = fmaf(xv, w.y, acc[4*j4+1]);
                acc[4*j4+2] = fmaf(xv, w.z, acc[4*j4+2]);
                acc[4*j4+3] = fmaf(xv, w.w, acc[4*j4+3]);
            }
        }
    }

    float4* Hrow = (float4*)(H + (size_t)row * DOUT);
    #pragma unroll
    for (int j4 = 0; j4 < DOUT / 4; j4++)
        Hrow[j4] = make_float4(acc[4*j4+0], acc[4*j4+1], acc[4*j4+2], acc[4*j4+3]);
}

// ---------------------------------------------------------------------------
// CSR row pointers from sorted dst: row_ptr[n] = lower_bound(dst, n)
// ---------------------------------------------------------------------------
__global__ void rowptr_kernel(const int* __restrict__ dst)
{
    int n = blockIdx.x * blockDim.x + threadIdx.x;
    if (n > NNODE) return;
    int lo = 0, hi = NEDGE;
    while (lo < hi) {
        int mid = (lo + hi) >> 1;
        if (__ldg(&dst[mid]) < n) lo = mid + 1; else hi = mid;
    }
    g_row_ptr[n] = lo;
}

// ---------------------------------------------------------------------------
// Attention: one warp per (batch, dst node); online softmax over incoming edges.
// Lane holds elements [2*lane, 2*lane+1] of the 64-wide feature vector.
// ---------------------------------------------------------------------------
__global__ void attn_kernel(const int* __restrict__ src, float* __restrict__ out)
{
    const int gw   = (blockIdx.x * blockDim.x + threadIdx.x) >> 5;
    const int lane = threadIdx.x & 31;
    if (gw >= BATCH * NNODE) return;
    const int b    = gw / NNODE;
    const int node = gw - b * NNODE;

    const float* __restrict__ hk = g_h + (size_t)b * NNODE * DOUT;
    const float* __restrict__ hv = g_h + (size_t)(BATCH + b) * NNODE * DOUT;

    const int lo = g_row_ptr[node];
    const int hi = g_row_ptr[node + 1];

    const float2 kd = *(const float2*)(hk + (size_t)node * DOUT + lane * 2);

    float m = -1e30f;
    float denom = 0.f;
    float2 acc = make_float2(0.f, 0.f);

    for (int e = lo; e < hi; e++) {
        const int s = __ldg(&src[e]);
        const float2 ks = *(const float2*)(hk + (size_t)s * DOUT + lane * 2);
        const float2 vs = *(const float2*)(hv + (size_t)s * DOUT + lane * 2);

        float p = kd.x * ks.x + kd.y * ks.y;
        #pragma unroll
        for (int o = 16; o > 0; o >>= 1) p += __shfl_xor_sync(0xffffffffu, p, o);

        const float mn    = fmaxf(m, p);
        const float scale = __expf(m - mn);   // m=-1e30 initially -> underflows to 0
        const float w     = __expf(p - mn);
        denom = denom * scale + w;
        acc.x = acc.x * scale + w * vs.x;
        acc.y = acc.y * scale + w * vs.y;
        m = mn;
    }

    const float inv = (denom > 0.f) ? (1.f / denom) : 0.f;
    float ox = acc.x * inv;
    float oy = acc.y * inv;
    ox = (ox >= 0.f) ? ox : NEG_SLOPE * ox;
    oy = (oy >= 0.f) ? oy : NEG_SLOPE * oy;

    *(float2*)(out + ((size_t)b * NNODE + node) * DOUT + lane * 2) = make_float2(ox, oy);
}

// ---------------------------------------------------------------------------
extern "C" void kernel_launch(void* const* d_in, const int* in_sizes, int n_in,
                              void* d_out, int out_size)
{
    const float* Xk = (const float*)d_in[0];
    const float* Xv = (const float*)d_in[1];
    const float* Wk = (const float*)d_in[2];
    const float* bk = (const float*)d_in[3];
    const float* Wv = (const float*)d_in[4];
    const float* bv = (const float*)d_in[5];
    const int*   src = (const int*)d_in[6];
    const int*   dst = (const int*)d_in[7];
    float* out = (float*)d_out;

    dim3 ggrid((BATCH * NNODE + 127) / 128, 2);
    gemm_kernel<<<ggrid, 128>>>(Xk, Xv, Wk, bk, Wv, bv);

    rowptr_kernel<<<(NNODE + 1 + 255) / 256, 256>>>(dst);

    const int total_warps = BATCH * NNODE;
    attn_kernel<<<(total_warps * 32 + 255) / 256, 256>>>(src, out);
}

// round 2
// speedup vs baseline: 1.2744x; 1.2744x over previous
#include <cuda_runtime.h>
#include <math.h>

#define BATCH 2
#define NNODE 50000
#define DIN 128
#define DOUT 64
#define NEDGE 800000
#define NEG_SLOPE 0.2f
#define ROWS_TOTAL (BATCH * NNODE)

typedef unsigned long long u64;

// Scratch: h[which][b][node][d], which: 0 = key, 1 = value. 51.2 MB total.
__device__ float g_h[2ull * BATCH * NNODE * DOUT];
__device__ int g_row_ptr[NNODE + 1];

// ---------------------------------------------------------------------------
// Packed f32x2 helpers (Blackwell FFMA2 path)
// ---------------------------------------------------------------------------
__device__ __forceinline__ u64 pack2(float x, float y) {
    u64 r;
    asm("mov.b64 %0, {%1, %2};" : "=l"(r) : "f"(x), "f"(y));
    return r;
}
__device__ __forceinline__ void ffma2(u64& acc, u64 a, u64 b) {
    asm("fma.rn.f32x2 %0, %1, %2, %0;" : "+l"(acc) : "l"(a), "l"(b));
}
__device__ __forceinline__ void unpack2(u64 v, float& lo, float& hi) {
    asm("mov.b64 {%0, %1}, %2;" : "=f"(lo), "=f"(hi) : "l"(v));
}

// ---------------------------------------------------------------------------
// Register-tiled GEMM: H = X @ W + b.  blockIdx.y selects (key|value) GEMM.
// Block = 128 threads; tile 128(M) x 64(N, full DOUT); K-tile = 16.
// Thread (tm,tn): rows tm*8..tm*8+7 (as 4 f32x2 row-pairs), cols tn*8..tn*8+7.
// ---------------------------------------------------------------------------
#define KT 16
#define APAD 4

__global__ void __launch_bounds__(128, 4)
gemm_kernel(const float* __restrict__ Xk, const float* __restrict__ Xv,
            const float* __restrict__ Wk, const float* __restrict__ bk,
            const float* __restrict__ Wv, const float* __restrict__ bv)
{
    const int which = blockIdx.y;
    const float* __restrict__ X    = which ? Xv : Xk;
    const float* __restrict__ W    = which ? Wv : Wk;
    const float* __restrict__ bias = which ? bv : bk;
    float* __restrict__ H = g_h + (size_t)which * BATCH * NNODE * DOUT;

    __shared__ float Bs[DIN][DOUT];          // full W: 32 KB
    __shared__ float As[KT][128 + APAD];     // A tile transposed: 8.4 KB
    __shared__ float bsm[DOUT];

    const int tid = threadIdx.x;

    // Stage whole W + bias once
    for (int i = tid; i < DIN * DOUT / 4; i += 128)
        ((float4*)Bs)[i] = ((const float4*)W)[i];
    if (tid < DOUT) bsm[tid] = bias[tid];
    __syncthreads();

    const int row0 = blockIdx.x * 128;
    const int tm = tid >> 3;          // 0..15
    const int tn = tid & 7;           // 0..7
    const int c0 = tn * 8;

    // 32 packed accumulators: acc[i][j] = rows (tm*8+2i, tm*8+2i+1), col c0+j
    u64 acc[4][8];
    #pragma unroll
    for (int i = 0; i < 4; i++)
        #pragma unroll
        for (int j = 0; j < 8; j++)
            acc[i][j] = pack2(bsm[c0 + j], bsm[c0 + j]);

    const int myrow = row0 + tid;
    const bool rowok = (myrow < ROWS_TOTAL);
    const float4* __restrict__ Xrow = (const float4*)(X + (size_t)myrow * DIN);

    #pragma unroll 1
    for (int kt = 0; kt < DIN / KT; kt++) {
        // Stage A tile transposed: As[kk][r] = X[row0+r][kt*16+kk]
        float4 v0, v1, v2, v3;
        if (rowok) {
            v0 = Xrow[kt * 4 + 0]; v1 = Xrow[kt * 4 + 1];
            v2 = Xrow[kt * 4 + 2]; v3 = Xrow[kt * 4 + 3];
        } else {
            v0 = v1 = v2 = v3 = make_float4(0.f, 0.f, 0.f, 0.f);
        }
        __syncthreads();   // previous iteration's reads done
        As[ 0][tid] = v0.x; As[ 1][tid] = v0.y; As[ 2][tid] = v0.z; As[ 3][tid] = v0.w;
        As[ 4][tid] = v1.x; As[ 5][tid] = v1.y; As[ 6][tid] = v1.z; As[ 7][tid] = v1.w;
        As[ 8][tid] = v2.x; As[ 9][tid] = v2.y; As[10][tid] = v2.z; As[11][tid] = v2.w;
        As[12][tid] = v3.x; As[13][tid] = v3.y; As[14][tid] = v3.z; As[15][tid] = v3.w;
        __syncthreads();

        #pragma unroll
        for (int kk = 0; kk < KT; kk++) {
            // A fragment: 4 row-pairs, directly packed from smem (16B aligned)
            const u64* ap = (const u64*)&As[kk][tm * 8];
            ulonglong2 aa0 = *(const ulonglong2*)(ap);
            ulonglong2 aa1 = *(const ulonglong2*)(ap + 2);
            u64 a2[4] = { aa0.x, aa0.y, aa1.x, aa1.y };

            // B fragment: 8 scalars, duplicated into packs
            const float4* bp = (const float4*)&Bs[kt * KT + kk][c0];
            float4 b0 = bp[0], b1 = bp[1];
            u64 bb[8];
            bb[0] = pack2(b0.x, b0.x); bb[1] = pack2(b0.y, b0.y);
            bb[2] = pack2(b0.z, b0.z); bb[3] = pack2(b0.w, b0.w);
            bb[4] = pack2(b1.x, b1.x); bb[5] = pack2(b1.y, b1.y);
            bb[6] = pack2(b1.z, b1.z); bb[7] = pack2(b1.w, b1.w);

            #pragma unroll
            for (int i = 0; i < 4; i++)
                #pragma unroll
                for (int j = 0; j < 8; j++)
                    ffma2(acc[i][j], a2[i], bb[j]);
        }
    }

    // Write back: per row-pair, unpack and store 2 float4 per row
    #pragma unroll
    for (int i = 0; i < 4; i++) {
        const int rA = row0 + tm * 8 + 2 * i;
        const int rB = rA + 1;
        float lo[8], hi[8];
        #pragma unroll
        for (int j = 0; j < 8; j++) unpack2(acc[i][j], lo[j], hi[j]);
        if (rA < ROWS_TOTAL) {
            float4* p = (float4*)(H + (size_t)rA * DOUT + c0);
            p[0] = make_float4(lo[0], lo[1], lo[2], lo[3]);
            p[1] = make_float4(lo[4], lo[5], lo[6], lo[7]);
        }
        if (rB < ROWS_TOTAL) {
            float4* p = (float4*)(H + (size_t)rB * DOUT + c0);
            p[0] = make_float4(hi[0], hi[1], hi[2], hi[3]);
            p[1] = make_float4(hi[4], hi[5], hi[6], hi[7]);
        }
    }
}

// ---------------------------------------------------------------------------
// CSR row pointers from sorted dst: row_ptr[n] = lower_bound(dst, n)
// ---------------------------------------------------------------------------
__global__ void rowptr_kernel(const int* __restrict__ dst)
{
    int n = blockIdx.x * blockDim.x + threadIdx.x;
    if (n > NNODE) return;
    int lo = 0, hi = NEDGE;
    while (lo < hi) {
        int mid = (lo + hi) >> 1;
        if (__ldg(&dst[mid]) < n) lo = mid + 1; else hi = mid;
    }
    g_row_ptr[n] = lo;
}

// ---------------------------------------------------------------------------
// Attention: one warp per (batch, dst node); online softmax over incoming edges.
// Lane holds elements [2*lane, 2*lane+1] of the 64-wide feature vector.
// ---------------------------------------------------------------------------
__global__ void attn_kernel(const int* __restrict__ src, float* __restrict__ out)
{
    const int gw   = (blockIdx.x * blockDim.x + threadIdx.x) >> 5;
    const int lane = threadIdx.x & 31;
    if (gw >= BATCH * NNODE) return;
    const int b    = gw / NNODE;
    const int node = gw - b * NNODE;

    const float* __restrict__ hk = g_h + (size_t)b * NNODE * DOUT;
    const float* __restrict__ hv = g_h + (size_t)(BATCH + b) * NNODE * DOUT;

    const int lo = g_row_ptr[node];
    const int hi = g_row_ptr[node + 1];

    const float2 kd = *(const float2*)(hk + (size_t)node * DOUT + lane * 2);

    float m = -1e30f;
    float denom = 0.f;
    float2 acc = make_float2(0.f, 0.f);

    for (int e = lo; e < hi; e++) {
        const int s = __ldg(&src[e]);
        const float2 ks = *(const float2*)(hk + (size_t)s * DOUT + lane * 2);
        const float2 vs = *(const float2*)(hv + (size_t)s * DOUT + lane * 2);

        float p = kd.x * ks.x + kd.y * ks.y;
        #pragma unroll
        for (int o = 16; o > 0; o >>= 1) p += __shfl_xor_sync(0xffffffffu, p, o);

        const float mn    = fmaxf(m, p);
        const float scale = __expf(m - mn);   // m=-1e30 initially -> underflows to 0
        const float w     = __expf(p - mn);
        denom = denom * scale + w;
        acc.x = acc.x * scale + w * vs.x;
        acc.y = acc.y * scale + w * vs.y;
        m = mn;
    }

    const float inv = (denom > 0.f) ? (1.f / denom) : 0.f;
    float ox = acc.x * inv;
    float oy = acc.y * inv;
    ox = (ox >= 0.f) ? ox : NEG_SLOPE * ox;
    oy = (oy >= 0.f) ? oy : NEG_SLOPE * oy;

    *(float2*)(out + ((size_t)b * NNODE + node) * DOUT + lane * 2) = make_float2(ox, oy);
}

// ---------------------------------------------------------------------------
extern "C" void kernel_launch(void* const* d_in, const int* in_sizes, int n_in,
                              void* d_out, int out_size)
{
    const float* Xk = (const float*)d_in[0];
    const float* Xv = (const float*)d_in[1];
    const float* Wk = (const float*)d_in[2];
    const float* bk = (const float*)d_in[3];
    const float* Wv = (const float*)d_in[4];
    const float* bv = (const float*)d_in[5];
    const int*   src = (const int*)d_in[6];
    const int*   dst = (const int*)d_in[7];
    float* out = (float*)d_out;

    dim3 ggrid((ROWS_TOTAL + 127) / 128, 2);
    gemm_kernel<<<ggrid, 128>>>(Xk, Xv, Wk, bk, Wv, bv);

    rowptr_kernel<<<(NNODE + 1 + 255) / 256, 256>>>(dst);

    const int total_warps = BATCH * NNODE;
    attn_kernel<<<(total_warps * 32 + 255) / 256, 256>>>(src, out);
}

// round 4
// speedup vs baseline: 1.2765x; 1.0017x over previous
#include <cuda_runtime.h>
#include <cuda_fp16.h>
#include <math.h>

#define BATCH 2
#define NNODE 50000
#define DIN 128
#define DOUT 64
#define NEDGE 800000
#define NEG_SLOPE 0.2f
#define ROWS_TOTAL (BATCH * NNODE)
#define KT 16
#define NKT (DIN / KT)

typedef unsigned long long u64;

// Scratch: key features fp32 (25.6 MB), value features fp16 (12.8 MB)
__device__ float  g_hk[(size_t)BATCH * NNODE * DOUT];
__device__ __half g_hv[(size_t)BATCH * NNODE * DOUT];
__device__ int    g_row_ptr[NNODE + 1];

// ---------------------------------------------------------------------------
// Packed f32x2 helpers (Blackwell FFMA2 path)
// ---------------------------------------------------------------------------
__device__ __forceinline__ u64 pack2(float x, float y) {
    u64 r;
    asm("mov.b64 %0, {%1, %2};" : "=l"(r) : "f"(x), "f"(y));
    return r;
}
__device__ __forceinline__ void ffma2(u64& acc, u64 a, u64 b) {
    asm("fma.rn.f32x2 %0, %1, %2, %0;" : "+l"(acc) : "l"(a), "l"(b));
}
__device__ __forceinline__ void unpack2(u64 v, float& lo, float& hi) {
    asm("mov.b64 {%0, %1}, %2;" : "=f"(lo), "=f"(hi) : "l"(v));
}

// ---------------------------------------------------------------------------
// Register-tiled GEMM: H = X @ W + b.  blockIdx.y selects (key|value) GEMM.
// Block = 128 threads; tile 128(M) x 64(N, full DOUT); K-tile = 16.
// Software-pipelined: prefetch tile kt+2 regs while computing kt, STS kt+1.
// Thread (tm,tn): rows tm*8..tm*8+7 (4 f32x2 row-pairs), cols tn*8..tn*8+7.
// key GEMM writes fp32, value GEMM writes fp16.
// ---------------------------------------------------------------------------
__global__ void __launch_bounds__(128, 4)
gemm_kernel(const float* __restrict__ Xk, const float* __restrict__ Xv,
            const float* __restrict__ Wk, const float* __restrict__ bk,
            const float* __restrict__ Wv, const float* __restrict__ bv)
{
    const int which = blockIdx.y;
    const float* __restrict__ X    = which ? Xv : Xk;
    const float* __restrict__ W    = which ? Wv : Wk;
    const float* __restrict__ bias = which ? bv : bk;

    __shared__ float Bs[DIN][DOUT];      // full W: 32 KB
    __shared__ float As[2][KT][128];     // double-buffered A tile (transposed): 16 KB
                                         // total = 48 KB exactly

    const int tid = threadIdx.x;

    // Stage whole W once
    for (int i = tid; i < DIN * DOUT / 4; i += 128)
        ((float4*)Bs)[i] = ((const float4*)W)[i];

    const int row0 = blockIdx.x * 128;
    const int tm = tid >> 3;          // 0..15
    const int tn = tid & 7;           // 0..7
    const int c0 = tn * 8;

    // 32 packed accumulators, init from bias (global, L1-cached broadcast)
    u64 acc[4][8];
    #pragma unroll
    for (int j = 0; j < 8; j++) {
        float b = __ldg(&bias[c0 + j]);
        u64 p = pack2(b, b);
        #pragma unroll
        for (int i = 0; i < 4; i++) acc[i][j] = p;
    }

    const int myrow = row0 + tid;
    const bool rowok = (myrow < ROWS_TOTAL);
    const float4* __restrict__ Xrow = (const float4*)(X + (size_t)myrow * DIN);

    float4 v0, v1, v2, v3;
    const float4 z4 = make_float4(0.f, 0.f, 0.f, 0.f);

    // prologue: load tile 0, stage it, load tile 1
    if (rowok) { v0 = Xrow[0]; v1 = Xrow[1]; v2 = Xrow[2]; v3 = Xrow[3]; }
    else       { v0 = v1 = v2 = v3 = z4; }
    {
        float* a0 = &As[0][0][tid];
        a0[0*128]=v0.x; a0[1*128]=v0.y; a0[2*128]=v0.z; a0[3*128]=v0.w;
        a0[4*128]=v1.x; a0[5*128]=v1.y; a0[6*128]=v1.z; a0[7*128]=v1.w;
        a0[8*128]=v2.x; a0[9*128]=v2.y; a0[10*128]=v2.z; a0[11*128]=v2.w;
        a0[12*128]=v3.x; a0[13*128]=v3.y; a0[14*128]=v3.z; a0[15*128]=v3.w;
    }
    if (rowok) { v0 = Xrow[4]; v1 = Xrow[5]; v2 = Xrow[6]; v3 = Xrow[7]; }
    else       { v0 = v1 = v2 = v3 = z4; }
    __syncthreads();

    int buf = 0;
    #pragma unroll 1
    for (int kt = 0; kt < NKT; kt++) {
        // compute on As[buf]
        #pragma unroll
        for (int kk = 0; kk < KT; kk++) {
            const u64* ap = (const u64*)&As[buf][kk][tm * 8];
            ulonglong2 aa0 = *(const ulonglong2*)(ap);
            ulonglong2 aa1 = *(const ulonglong2*)(ap + 2);
            u64 a2[4] = { aa0.x, aa0.y, aa1.x, aa1.y };

            const float4* bp = (const float4*)&Bs[kt * KT + kk][c0];
            float4 b0 = bp[0], b1 = bp[1];
            u64 bb[8];
            bb[0] = pack2(b0.x, b0.x); bb[1] = pack2(b0.y, b0.y);
            bb[2] = pack2(b0.z, b0.z); bb[3] = pack2(b0.w, b0.w);
            bb[4] = pack2(b1.x, b1.x); bb[5] = pack2(b1.y, b1.y);
            bb[6] = pack2(b1.z, b1.z); bb[7] = pack2(b1.w, b1.w);

            #pragma unroll
            for (int i = 0; i < 4; i++)
                #pragma unroll
                for (int j = 0; j < 8; j++)
                    ffma2(acc[i][j], a2[i], bb[j]);
        }

        if (kt < NKT - 1) {
            // stage tile kt+1 (regs already loaded) into the other buffer
            float* a0 = &As[buf ^ 1][0][tid];
            a0[0*128]=v0.x; a0[1*128]=v0.y; a0[2*128]=v0.z; a0[3*128]=v0.w;
            a0[4*128]=v1.x; a0[5*128]=v1.y; a0[6*128]=v1.z; a0[7*128]=v1.w;
            a0[8*128]=v2.x; a0[9*128]=v2.y; a0[10*128]=v2.z; a0[11*128]=v2.w;
            a0[12*128]=v3.x; a0[13*128]=v3.y; a0[14*128]=v3.z; a0[15*128]=v3.w;
            // prefetch tile kt+2
            if (kt < NKT - 2) {
                int kb = (kt + 2) * 4;
                if (rowok) { v0 = Xrow[kb]; v1 = Xrow[kb+1]; v2 = Xrow[kb+2]; v3 = Xrow[kb+3]; }
                else       { v0 = v1 = v2 = v3 = z4; }
            }
            __syncthreads();
            buf ^= 1;
        }
    }

    // Epilogue
    #pragma unroll
    for (int i = 0; i < 4; i++) {
        const int rA = row0 + tm * 8 + 2 * i;
        const int rB = rA + 1;
        float lo[8], hi[8];
        #pragma unroll
        for (int j = 0; j < 8; j++) unpack2(acc[i][j], lo[j], hi[j]);

        if (which == 0) {
            if (rA < ROWS_TOTAL) {
                float4* p = (float4*)(g_hk + (size_t)rA * DOUT + c0);
                p[0] = make_float4(lo[0], lo[1], lo[2], lo[3]);
                p[1] = make_float4(lo[4], lo[5], lo[6], lo[7]);
            }
            if (rB < ROWS_TOTAL) {
                float4* p = (float4*)(g_hk + (size_t)rB * DOUT + c0);
                p[0] = make_float4(hi[0], hi[1], hi[2], hi[3]);
                p[1] = make_float4(hi[4], hi[5], hi[6], hi[7]);
            }
        } else {
            if (rA < ROWS_TOTAL) {
                __half2 hs[4];
                hs[0] = __floats2half2_rn(lo[0], lo[1]);
                hs[1] = __floats2half2_rn(lo[2], lo[3]);
                hs[2] = __floats2half2_rn(lo[4], lo[5]);
                hs[3] = __floats2half2_rn(lo[6], lo[7]);
                *(uint4*)(g_hv + (size_t)rA * DOUT + c0) = *(const uint4*)hs;
            }
            if (rB < ROWS_TOTAL) {
                __half2 hs[4];
                hs[0] = __floats2half2_rn(hi[0], hi[1]);
                hs[1] = __floats2half2_rn(hi[2], hi[3]);
                hs[2] = __floats2half2_rn(hi[4], hi[5]);
                hs[3] = __floats2half2_rn(hi[6], hi[7]);
                *(uint4*)(g_hv + (size_t)rB * DOUT + c0) = *(const uint4*)hs;
            }
        }
    }
}

// ---------------------------------------------------------------------------
// CSR row pointers from sorted dst: row_ptr[n] = lower_bound(dst, n)
// ---------------------------------------------------------------------------
__global__ void rowptr_kernel(const int* __restrict__ dst)
{
    int n = blockIdx.x * blockDim.x + threadIdx.x;
    if (n > NNODE) return;
    int lo = 0, hi = NEDGE;
    while (lo < hi) {
        int mid = (lo + hi) >> 1;
        if (__ldg(&dst[mid]) < n) lo = mid + 1; else hi = mid;
    }
    g_row_ptr[n] = lo;
}

// ---------------------------------------------------------------------------
// Attention: one warp per (batch, dst node); online softmax over incoming edges.
// Lane holds elements [2*lane, 2*lane+1]. Keys fp32, values fp16 gather.
// ---------------------------------------------------------------------------
__global__ void attn_kernel(const int* __restrict__ src, float* __restrict__ out)
{
    const int gw   = (blockIdx.x * blockDim.x + threadIdx.x) >> 5;
    const int lane = threadIdx.x & 31;
    if (gw >= BATCH * NNODE) return;
    const int b    = gw / NNODE;
    const int node = gw - b * NNODE;

    const float*  __restrict__ hk = g_hk + (size_t)b * NNODE * DOUT;
    const __half* __restrict__ hv = g_hv + (size_t)b * NNODE * DOUT;

    const int lo = g_row_ptr[node];
    const int hi = g_row_ptr[node + 1];

    const float2 kd = *(const float2*)(hk + (size_t)node * DOUT + lane * 2);

    float m = -1e30f;
    float denom = 0.f;
    float2 acc = make_float2(0.f, 0.f);

    for (int e = lo; e < hi; e++) {
        const int s = __ldg(&src[e]);
        const float2  ks = *(const float2*)(hk + (size_t)s * DOUT + lane * 2);
        const __half2 vh = *(const __half2*)(hv + (size_t)s * DOUT + lane * 2);
        const float2  vs = __half22float2(vh);

        float p = kd.x * ks.x + kd.y * ks.y;
        #pragma unroll
        for (int o = 16; o > 0; o >>= 1) p += __shfl_xor_sync(0xffffffffu, p, o);

        const float mn    = fmaxf(m, p);
        const float scale = __expf(m - mn);   // m=-1e30 initially -> underflows to 0
        const float w     = __expf(p - mn);
        denom = denom * scale + w;
        acc.x = acc.x * scale + w * vs.x;
        acc.y = acc.y * scale + w * vs.y;
        m = mn;
    }

    const float inv = (denom > 0.f) ? (1.f / denom) : 0.f;
    float ox = acc.x * inv;
    float oy = acc.y * inv;
    ox = (ox >= 0.f) ? ox : NEG_SLOPE * ox;
    oy = (oy >= 0.f) ? oy : NEG_SLOPE * oy;

    *(float2*)(out + ((size_t)b * NNODE + node) * DOUT + lane * 2) = make_float2(ox, oy);
}

// ---------------------------------------------------------------------------
extern "C" void kernel_launch(void* const* d_in, const int* in_sizes, int n_in,
                              void* d_out, int out_size)
{
    const float* Xk = (const float*)d_in[0];
    const float* Xv = (const float*)d_in[1];
    const float* Wk = (const float*)d_in[2];
    const float* bk = (const float*)d_in[3];
    const float* Wv = (const float*)d_in[4];
    const float* bv = (const float*)d_in[5];
    const int*   src = (const int*)d_in[6];
    const int*   dst = (const int*)d_in[7];
    float* out = (float*)d_out;

    dim3 ggrid((ROWS_TOTAL + 127) / 128, 2);
    gemm_kernel<<<ggrid, 128>>>(Xk, Xv, Wk, bk, Wv, bv);

    rowptr_kernel<<<(NNODE + 1 + 255) / 256, 256>>>(dst);

    const int total_warps = BATCH * NNODE;
    attn_kernel<<<(total_warps * 32 + 255) / 256, 256>>>(src, out);
}

// round 7
// speedup vs baseline: 1.2884x; 1.0093x over previous
#include <cuda_runtime.h>
#include <cuda_fp16.h>
#include <math.h>

#define BATCH 2
#define NNODE 50000
#define DIN 128
#define DOUT 64
#define NEDGE 800000
#define NEG_SLOPE 0.2f
#define ROWS_TOTAL (BATCH * NNODE)
#define MBLK 128
#define GEMM_GRIDX ((ROWS_TOTAL + MBLK - 1) / MBLK)

// Scratch: key features fp32 (25.6 MB), value features fp16 (12.8 MB)
__device__ float  g_hk[(size_t)BATCH * NNODE * DOUT];
__device__ __half g_hv[(size_t)BATCH * NNODE * DOUT];
__device__ int    g_row_ptr[NNODE + 1];

// ---------------------------------------------------------------------------
// tf32 helpers
// ---------------------------------------------------------------------------
__device__ __forceinline__ unsigned to_tf32(float f) {
    unsigned u;
    asm("cvt.rna.tf32.f32 %0, %1;" : "=r"(u) : "f"(f));
    return u;
}
__device__ __forceinline__ void split_tf32(float f, unsigned& hi, unsigned& lo) {
    hi = to_tf32(f);
    lo = to_tf32(f - __uint_as_float(hi));
}
__device__ __forceinline__ void mma_tf32(float* d, const unsigned* a,
                                         unsigned b0, unsigned b1) {
    asm volatile(
        "mma.sync.aligned.m16n8k8.row.col.f32.tf32.tf32.f32 "
        "{%0,%1,%2,%3}, {%4,%5,%6,%7}, {%8,%9}, {%0,%1,%2,%3};"
        : "+f"(d[0]), "+f"(d[1]), "+f"(d[2]), "+f"(d[3])
        : "r"(a[0]), "r"(a[1]), "r"(a[2]), "r"(a[3]), "r"(b0), "r"(b1));
}

// B smem index with XOR swizzle (conflict-free fragment loads): W[k][n]
__device__ __forceinline__ int bidx(int k, int n) {
    return (k << 6) | (n ^ ((k & 3) << 3));
}
// A smem index: row-major 128x32 chunk, col XOR-swizzled by row
__device__ __forceinline__ int aidx(int row, int col) {
    return (row << 5) | (col ^ ((row & 7) << 2));
}

// ---------------------------------------------------------------------------
// 3xTF32 tensor-core GEMM: H = X @ W + b.  blockIdx.y: 0 = key(fp32), 1 = value(fp16)
// Block 128 thr = 4 warps; M-tile 128/block (32/warp as 2x m16), N = 64 full.
// W fp32 in smem (swizzled); hi/lo tf32 split done at fragment-load time.
// A staged per k32 chunk (single buffer); next chunk LDG issued pre-compute.
// Static smem = 32KB (Bs) + 16KB (As) = 48KB exactly. No CUDA API needed.
// ---------------------------------------------------------------------------
__global__ void __launch_bounds__(128)
gemm_kernel(const float* __restrict__ Xk, const float* __restrict__ Xv,
            const float* __restrict__ Wk, const float* __restrict__ bk,
            const float* __restrict__ Wv, const float* __restrict__ bv)
{
    __shared__ float Bs[DIN * DOUT];   // 32 KB
    __shared__ float As[MBLK * 32];    // 16 KB

    const int which = blockIdx.y;
    const float* __restrict__ X    = which ? Xv : Xk;
    const float* __restrict__ W    = which ? Wv : Wk;
    const float* __restrict__ bias = which ? bv : bk;

    const int tid  = threadIdx.x;
    const int warp = tid >> 5;
    const int lane = tid & 31;
    const int g    = lane >> 2;   // 0..7
    const int tig  = lane & 3;    // 0..3

    // --- Stage W fp32 (swizzled) ---
    for (int i = tid; i < DIN * DOUT; i += 128) {
        int k = i >> 6, n = i & 63;
        Bs[bidx(k, n)] = W[i];
    }

    const int row0  = blockIdx.x * MBLK;
    const int myrow = row0 + tid;
    const bool rowok = (myrow < ROWS_TOTAL);
    const float4* __restrict__ Xrow = (const float4*)(X + (size_t)myrow * DIN);
    const float4 z4 = make_float4(0.f, 0.f, 0.f, 0.f);

    float acc[2][8][4];
    #pragma unroll
    for (int t = 0; t < 2; t++)
        #pragma unroll
        for (int nt = 0; nt < 8; nt++)
            #pragma unroll
            for (int i = 0; i < 4; i++) acc[t][nt][i] = 0.f;

    // A staging: thread = row, 8 float4 per k32 chunk, swizzled stores
    float4 pf[8];
    #pragma unroll
    for (int j = 0; j < 8; j++) pf[j] = rowok ? Xrow[j] : z4;   // chunk 0
    #pragma unroll
    for (int j = 0; j < 8; j++)
        *(float4*)&As[aidx(tid, j * 4)] = pf[j];
    __syncthreads();

    #pragma unroll 1
    for (int c = 0; c < 4; c++) {
        // issue next chunk's global loads early (overlap with compute)
        if (c < 3) {
            #pragma unroll
            for (int j = 0; j < 8; j++)
                pf[j] = rowok ? Xrow[(c + 1) * 8 + j] : z4;
        }

        #pragma unroll
        for (int k8 = 0; k8 < 4; k8++) {
            const int k0 = k8 * 8;
            // A fragments for 2 m16 tiles, hi/lo split on the fly
            unsigned ahi[2][4], alo[2][4];
            #pragma unroll
            for (int t = 0; t < 2; t++) {
                const int r = warp * 32 + t * 16 + g;
                float af[4];
                af[0] = As[aidx(r,     k0 + tig)];
                af[1] = As[aidx(r + 8, k0 + tig)];
                af[2] = As[aidx(r,     k0 + tig + 4)];
                af[3] = As[aidx(r + 8, k0 + tig + 4)];
                #pragma unroll
                for (int i = 0; i < 4; i++)
                    split_tf32(af[i], ahi[t][i], alo[t][i]);
            }
            const int kg0 = c * 32 + k0 + tig;   // global k of b0 row
            const int kg1 = kg0 + 4;
            #pragma unroll
            for (int nt = 0; nt < 8; nt++) {
                const int n = nt * 8 + g;
                unsigned bh0, bl0, bh1, bl1;
                split_tf32(Bs[bidx(kg0, n)], bh0, bl0);
                split_tf32(Bs[bidx(kg1, n)], bh1, bl1);
                #pragma unroll
                for (int t = 0; t < 2; t++) {
                    mma_tf32(acc[t][nt], ahi[t], bh0, bh1);
                    mma_tf32(acc[t][nt], ahi[t], bl0, bl1);
                    mma_tf32(acc[t][nt], alo[t], bh0, bh1);
                }
            }
        }

        if (c < 3) {
            __syncthreads();   // all warps done reading As
            #pragma unroll
            for (int j = 0; j < 8; j++)
                *(float4*)&As[aidx(tid, j * 4)] = pf[j];
            __syncthreads();
        }
    }

    // --- Epilogue: add bias, store (fp32 keys / fp16 values) ---
    #pragma unroll
    for (int t = 0; t < 2; t++) {
        const int r0 = row0 + warp * 32 + t * 16 + g;
        const int r1 = r0 + 8;
        #pragma unroll
        for (int nt = 0; nt < 8; nt++) {
            const int col = nt * 8 + tig * 2;
            const float bx = __ldg(&bias[col]);
            const float by = __ldg(&bias[col + 1]);
            float d0 = acc[t][nt][0] + bx, d1 = acc[t][nt][1] + by;
            float d2 = acc[t][nt][2] + bx, d3 = acc[t][nt][3] + by;
            if (which == 0) {
                if (r0 < ROWS_TOTAL)
                    *(float2*)(g_hk + (size_t)r0 * DOUT + col) = make_float2(d0, d1);
                if (r1 < ROWS_TOTAL)
                    *(float2*)(g_hk + (size_t)r1 * DOUT + col) = make_float2(d2, d3);
            } else {
                if (r0 < ROWS_TOTAL)
                    *(__half2*)(g_hv + (size_t)r0 * DOUT + col) = __floats2half2_rn(d0, d1);
                if (r1 < ROWS_TOTAL)
                    *(__half2*)(g_hv + (size_t)r1 * DOUT + col) = __floats2half2_rn(d2, d3);
            }
        }
    }
}

// ---------------------------------------------------------------------------
// CSR row pointers from sorted dst: row_ptr[n] = lower_bound(dst, n)
// ---------------------------------------------------------------------------
__global__ void rowptr_kernel(const int* __restrict__ dst)
{
    int n = blockIdx.x * blockDim.x + threadIdx.x;
    if (n > NNODE) return;
    int lo = 0, hi = NEDGE;
    while (lo < hi) {
        int mid = (lo + hi) >> 1;
        if (__ldg(&dst[mid]) < n) lo = mid + 1; else hi = mid;
    }
    g_row_ptr[n] = lo;
}

// ---------------------------------------------------------------------------
// Attention: one warp per (batch, dst node); 4 edges processed concurrently by
// four 8-lane groups (g = lane>>3); lane holds features [sub*8, sub*8+8).
// Online softmax per group, flash-merge across groups at the end.
// ---------------------------------------------------------------------------
__global__ void attn_kernel(const int* __restrict__ src, float* __restrict__ out)
{
    const int gw   = (blockIdx.x * blockDim.x + threadIdx.x) >> 5;
    const int lane = threadIdx.x & 31;
    if (gw >= BATCH * NNODE) return;
    const int b    = gw / NNODE;
    const int node = gw - b * NNODE;
    const int g    = lane >> 3;   // edge slot 0..3
    const int sub  = lane & 7;    // feature octet 0..7

    const float*  __restrict__ hk = g_hk + (size_t)b * NNODE * DOUT;
    const __half* __restrict__ hv = g_hv + (size_t)b * NNODE * DOUT;

    const int lo = g_row_ptr[node];
    const int hi = g_row_ptr[node + 1];

    const float4 kd0 = *(const float4*)(hk + (size_t)node * DOUT + sub * 8);
    const float4 kd1 = *(const float4*)(hk + (size_t)node * DOUT + sub * 8 + 4);

    float m = -1e30f;
    float denom = 0.f;
    float4 acc0 = make_float4(0.f, 0.f, 0.f, 0.f);
    float4 acc1 = make_float4(0.f, 0.f, 0.f, 0.f);

    for (int e0 = lo; e0 < hi; e0 += 4) {
        const int e = e0 + g;
        const bool valid = (e < hi);
        const int s = __ldg(&src[valid ? e : lo]);

        const float4 ks0 = *(const float4*)(hk + (size_t)s * DOUT + sub * 8);
        const float4 ks1 = *(const float4*)(hk + (size_t)s * DOUT + sub * 8 + 4);
        const uint4  vu  = *(const uint4*)(hv + (size_t)s * DOUT + sub * 8);
        const float2 v0 = __half22float2(*(const __half2*)&vu.x);
        const float2 v1 = __half22float2(*(const __half2*)&vu.y);
        const float2 v2 = __half22float2(*(const __half2*)&vu.z);
        const float2 v3 = __half22float2(*(const __half2*)&vu.w);

        float p = kd0.x * ks0.x + kd0.y * ks0.y + kd0.z * ks0.z + kd0.w * ks0.w
                + kd1.x * ks1.x + kd1.y * ks1.y + kd1.z * ks1.z + kd1.w * ks1.w;
        p += __shfl_xor_sync(0xffffffffu, p, 1);
        p += __shfl_xor_sync(0xffffffffu, p, 2);
        p += __shfl_xor_sync(0xffffffffu, p, 4);
        if (!valid) p = -INFINITY;

        const float mn    = fmaxf(m, p);
        const float scale = __expf(m - mn);
        const float w     = __expf(p - mn);
        m = mn;
        denom = denom * scale + w;
        acc0.x = acc0.x * scale + w * v0.x;  acc0.y = acc0.y * scale + w * v0.y;
        acc0.z = acc0.z * scale + w * v1.x;  acc0.w = acc0.w * scale + w * v1.y;
        acc1.x = acc1.x * scale + w * v2.x;  acc1.y = acc1.y * scale + w * v2.y;
        acc1.z = acc1.z * scale + w * v3.x;  acc1.w = acc1.w * scale + w * v3.y;
    }

    // merge the 4 groups (xor tree over offsets 8, 16)
    #pragma unroll
    for (int off = 8; off <= 16; off <<= 1) {
        const float m2 = __shfl_xor_sync(0xffffffffu, m, off);
        const float d2 = __shfl_xor_sync(0xffffffffu, denom, off);
        float a2[8];
        a2[0] = __shfl_xor_sync(0xffffffffu, acc0.x, off);
        a2[1] = __shfl_xor_sync(0xffffffffu, acc0.y, off);
        a2[2] = __shfl_xor_sync(0xffffffffu, acc0.z, off);
        a2[3] = __shfl_xor_sync(0xffffffffu, acc0.w, off);
        a2[4] = __shfl_xor_sync(0xffffffffu, acc1.x, off);
        a2[5] = __shfl_xor_sync(0xffffffffu, acc1.y, off);
        a2[6] = __shfl_xor_sync(0xffffffffu, acc1.z, off);
        a2[7] = __shfl_xor_sync(0xffffffffu, acc1.w, off);
        const float M  = fmaxf(m, m2);
        const float s1 = __expf(m - M);
        const float s2 = __expf(m2 - M);
        m = M;
        denom = denom * s1 + d2 * s2;
        acc0.x = acc0.x * s1 + a2[0] * s2;  acc0.y = acc0.y * s1 + a2[1] * s2;
        acc0.z = acc0.z * s1 + a2[2] * s2;  acc0.w = acc0.w * s1 + a2[3] * s2;
        acc1.x = acc1.x * s1 + a2[4] * s2;  acc1.y = acc1.y * s1 + a2[5] * s2;
        acc1.z = acc1.z * s1 + a2[6] * s2;  acc1.w = acc1.w * s1 + a2[7] * s2;
    }

    if (g == 0) {
        const float inv = (denom > 0.f) ? (1.f / denom) : 0.f;
        float o[8] = { acc0.x * inv, acc0.y * inv, acc0.z * inv, acc0.w * inv,
                       acc1.x * inv, acc1.y * inv, acc1.z * inv, acc1.w * inv };
        #pragma unroll
        for (int i = 0; i < 8; i++) o[i] = (o[i] >= 0.f) ? o[i] : NEG_SLOPE * o[i];
        float* op = out + ((size_t)b * NNODE + node) * DOUT + sub * 8;
        *(float4*)(op)     = make_float4(o[0], o[1], o[2], o[3]);
        *(float4*)(op + 4) = make_float4(o[4], o[5], o[6], o[7]);
    }
}

// ---------------------------------------------------------------------------
extern "C" void kernel_launch(void* const* d_in, const int* in_sizes, int n_in,
                              void* d_out, int out_size)
{
    const float* Xk = (const float*)d_in[0];
    const float* Xv = (const float*)d_in[1];
    const float* Wk = (const float*)d_in[2];
    const float* bk = (const float*)d_in[3];
    const float* Wv = (const float*)d_in[4];
    const float* bv = (const float*)d_in[5];
    const int*   src = (const int*)d_in[6];
    const int*   dst = (const int*)d_in[7];
    float* out = (float*)d_out;

    dim3 ggrid(GEMM_GRIDX, 2);
    gemm_kernel<<<ggrid, 128>>>(Xk, Xv, Wk, bk, Wv, bv);

    rowptr_kernel<<<(NNODE + 1 + 255) / 256, 256>>>(dst);

    const int total_warps = BATCH * NNODE;
    attn_kernel<<<(total_warps * 32 + 255) / 256, 256>>>(src, out);
}